// round 15
// baseline (speedup 1.0000x reference)
#include <cuda_runtime.h>
#include <math.h>

#define S_LEN 4096
#define DMODEL 768
#define NH 12
#define DH 64
#define BATCH 2
#define MROWS (BATCH*S_LEN)   // 8192
#define QSCALE 0.125f         // 1/sqrt(64)

// Scratch (module-load allocated; no runtime allocs)
__device__ float g_Q[(size_t)BATCH*NH*S_LEN*DH];
__device__ float g_K[(size_t)BATCH*NH*S_LEN*DH];
__device__ float g_V[(size_t)BATCH*NH*S_LEN*DH];
__device__ float g_ctx[(size_t)MROWS*DMODEL];

// ---------------------------------------------------------------------------
// QKV GEMM: C = X @ W[z], written into [B,H,S,Dh] layout.
// BM=128, BN=64, BK=16, 256 threads, 8x4 per thread.
// ---------------------------------------------------------------------------
__global__ __launch_bounds__(256) void qkv_gemm(
    const float* __restrict__ X,
    const float* __restrict__ Wq,
    const float* __restrict__ Wk,
    const float* __restrict__ Wv)
{
    const float* W = (blockIdx.z == 0) ? Wq : (blockIdx.z == 1) ? Wk : Wv;
    float* O       = (blockIdx.z == 0) ? g_Q : (blockIdx.z == 1) ? g_K : g_V;

    __shared__ float As[16][132];   // transposed A tile, padded
    __shared__ float Ws[16][64];

    const int bm = blockIdx.y * 128;
    const int bn = blockIdx.x * 64;
    const int tid = threadIdx.x;
    const int tx = tid & 15;
    const int ty = tid >> 4;

    float acc[8][4];
    #pragma unroll
    for (int i = 0; i < 8; i++)
        #pragma unroll
        for (int j = 0; j < 4; j++) acc[i][j] = 0.f;

    for (int k0 = 0; k0 < DMODEL; k0 += 16) {
        // A tile: 128x16 = 512 float4, 2 per thread (store transposed)
        #pragma unroll
        for (int l = 0; l < 2; l++) {
            int idx = tid + l * 256;
            int row = idx >> 2;
            int c4  = idx & 3;
            float4 a = *(const float4*)&X[(size_t)(bm + row) * DMODEL + k0 + c4 * 4];
            As[c4*4 + 0][row] = a.x;
            As[c4*4 + 1][row] = a.y;
            As[c4*4 + 2][row] = a.z;
            As[c4*4 + 3][row] = a.w;
        }
        // W tile: 16x64 = 256 float4, 1 per thread
        {
            int row = tid >> 4;
            int c4  = tid & 15;
            *(float4*)&Ws[row][c4 * 4] =
                *(const float4*)&W[(size_t)(k0 + row) * DMODEL + bn + c4 * 4];
        }
        __syncthreads();

        #pragma unroll
        for (int kk = 0; kk < 16; kk++) {
            float4 b = *(float4*)&Ws[kk][tx * 4];
            float a[8];
            #pragma unroll
            for (int i = 0; i < 8; i++) a[i] = As[kk][ty * 8 + i];
            #pragma unroll
            for (int i = 0; i < 8; i++) {
                acc[i][0] += a[i] * b.x;
                acc[i][1] += a[i] * b.y;
                acc[i][2] += a[i] * b.z;
                acc[i][3] += a[i] * b.w;
            }
        }
        __syncthreads();
    }

    // write into [B,H,S,Dh]: col n = bn + tx*4 + j (all same head since bn%64==0)
    const int h    = bn >> 6;
    const int dcol = tx * 4;
    #pragma unroll
    for (int i = 0; i < 8; i++) {
        int m = bm + ty * 8 + i;
        int b = m >> 12;
        int s = m & (S_LEN - 1);
        float4 r;
        r.x = acc[i][0]; r.y = acc[i][1]; r.z = acc[i][2]; r.w = acc[i][3];
        *(float4*)&O[(((size_t)(b * NH + h) * S_LEN) + s) * DH + dcol] = r;
    }
}

// ---------------------------------------------------------------------------
// Flash attention (causal), fp32. One CTA per (bh, 64-row q-tile).
// 256 threads: ty=tid/16 owns rows ty*4..ty*4+3, tx=tid%16.
// Score cols per thread: c = tx + 16*j (bank-friendly, stride-68 sK).
// Output dims per thread: d = tx*4..tx*4+3 (stride-64 sV, conflict-free).
// ---------------------------------------------------------------------------
__global__ __launch_bounds__(256) void attn_kernel()
{
    extern __shared__ float sm[];
    float* sQ = sm;                         // 64 x 64
    float* sK = sQ + 64 * 64;               // 64 x 68 (padded)
    float* sV = sK + 64 * 68;               // 64 x 64
    float* sP = sV + 64 * 64;               // 64 x 68 (padded)

    const int bh = blockIdx.y;
    const int qt = (gridDim.x - 1) - blockIdx.x;   // heavy tiles first
    const int q0 = qt * 64;
    const int tid = threadIdx.x;
    const int tx = tid & 15;
    const int ty = tid >> 4;

    const float* Qp = g_Q + (size_t)bh * S_LEN * DH + (size_t)q0 * DH;
    const float* Kb = g_K + (size_t)bh * S_LEN * DH;
    const float* Vb = g_V + (size_t)bh * S_LEN * DH;

    // load Q tile (scaled by 1/sqrt(Dh))
    #pragma unroll
    for (int l = 0; l < 4; l++) {
        int idx = tid + 256 * l;
        int row = idx >> 4;
        int c4  = idx & 15;
        float4 q = *(const float4*)&Qp[row * DH + c4 * 4];
        q.x *= QSCALE; q.y *= QSCALE; q.z *= QSCALE; q.w *= QSCALE;
        *(float4*)&sQ[row * 64 + c4 * 4] = q;
    }

    float m_i[4], l_i[4];
    float4 o4[4];
    #pragma unroll
    for (int i = 0; i < 4; i++) {
        m_i[i] = -1e30f;
        l_i[i] = 0.f;
        o4[i].x = 0.f; o4[i].y = 0.f; o4[i].z = 0.f; o4[i].w = 0.f;
    }

    for (int kt = 0; kt <= qt; kt++) {
        __syncthreads();   // prior PV reads done before overwriting K/V
        const int k0 = kt * 64;
        const float* Kp = Kb + (size_t)k0 * DH;
        const float* Vp = Vb + (size_t)k0 * DH;
        #pragma unroll
        for (int l = 0; l < 4; l++) {
            int idx = tid + 256 * l;
            int row = idx >> 4;
            int c4  = idx & 15;
            *(float4*)&sK[row * 68 + c4 * 4] = *(const float4*)&Kp[row * DH + c4 * 4];
            *(float4*)&sV[row * 64 + c4 * 4] = *(const float4*)&Vp[row * DH + c4 * 4];
        }
        __syncthreads();

        // scores: acc[i][j] = sum_d Qs[ty*4+i][d] * K[tx+16j][d]
        float acc[4][4];
        #pragma unroll
        for (int i = 0; i < 4; i++)
            #pragma unroll
            for (int j = 0; j < 4; j++) acc[i][j] = 0.f;

        #pragma unroll
        for (int d0 = 0; d0 < 64; d0 += 4) {
            float4 qv[4];
            #pragma unroll
            for (int i = 0; i < 4; i++)
                qv[i] = *(float4*)&sQ[(ty * 4 + i) * 64 + d0];
            #pragma unroll
            for (int j = 0; j < 4; j++) {
                float4 kv = *(float4*)&sK[(tx + 16 * j) * 68 + d0];
                #pragma unroll
                for (int i = 0; i < 4; i++) {
                    acc[i][j] += qv[i].x * kv.x + qv[i].y * kv.y
                               + qv[i].z * kv.z + qv[i].w * kv.w;
                }
            }
        }

        // causal mask (only the diagonal tile needs it)
        if (kt == qt) {
            #pragma unroll
            for (int i = 0; i < 4; i++) {
                int r = ty * 4 + i;
                #pragma unroll
                for (int j = 0; j < 4; j++) {
                    int c = tx + 16 * j;
                    if (c > r) acc[i][j] = -1e30f;
                }
            }
        }

        // online softmax update + P store
        #pragma unroll
        for (int i = 0; i < 4; i++) {
            float mt = fmaxf(fmaxf(acc[i][0], acc[i][1]),
                             fmaxf(acc[i][2], acc[i][3]));
            mt = fmaxf(mt, __shfl_xor_sync(0xffffffffu, mt, 8));
            mt = fmaxf(mt, __shfl_xor_sync(0xffffffffu, mt, 4));
            mt = fmaxf(mt, __shfl_xor_sync(0xffffffffu, mt, 2));
            mt = fmaxf(mt, __shfl_xor_sync(0xffffffffu, mt, 1));

            float mnew  = fmaxf(m_i[i], mt);
            float alpha = __expf(m_i[i] - mnew);
            float s = 0.f;
            #pragma unroll
            for (int j = 0; j < 4; j++) {
                float p = __expf(acc[i][j] - mnew);
                s += p;
                sP[(ty * 4 + i) * 68 + tx + 16 * j] = p;
            }
            s += __shfl_xor_sync(0xffffffffu, s, 8);
            s += __shfl_xor_sync(0xffffffffu, s, 4);
            s += __shfl_xor_sync(0xffffffffu, s, 2);
            s += __shfl_xor_sync(0xffffffffu, s, 1);

            l_i[i] = l_i[i] * alpha + s;
            m_i[i] = mnew;
            o4[i].x *= alpha; o4[i].y *= alpha; o4[i].z *= alpha; o4[i].w *= alpha;
        }
        __syncthreads();   // sP visible

        // PV: o4[i] += sum_c P[ty*4+i][c] * V[c][tx*4 .. tx*4+3]
        #pragma unroll 8
        for (int c = 0; c < 64; c++) {
            float4 vv = *(const float4*)&sV[c * 64 + tx * 4];
            float p0 = sP[(ty * 4 + 0) * 68 + c];
            float p1 = sP[(ty * 4 + 1) * 68 + c];
            float p2 = sP[(ty * 4 + 2) * 68 + c];
            float p3 = sP[(ty * 4 + 3) * 68 + c];
            o4[0].x += p0 * vv.x; o4[0].y += p0 * vv.y; o4[0].z += p0 * vv.z; o4[0].w += p0 * vv.w;
            o4[1].x += p1 * vv.x; o4[1].y += p1 * vv.y; o4[1].z += p1 * vv.z; o4[1].w += p1 * vv.w;
            o4[2].x += p2 * vv.x; o4[2].y += p2 * vv.y; o4[2].z += p2 * vv.z; o4[2].w += p2 * vv.w;
            o4[3].x += p3 * vv.x; o4[3].y += p3 * vv.y; o4[3].z += p3 * vv.z; o4[3].w += p3 * vv.w;
        }
    }

    // finalize: ctx layout [b, s, h*64+d]
    const int b = bh / NH;
    const int h = bh % NH;
    #pragma unroll
    for (int i = 0; i < 4; i++) {
        float inv = 1.f / l_i[i];
        float4 r;
        r.x = o4[i].x * inv; r.y = o4[i].y * inv;
        r.z = o4[i].z * inv; r.w = o4[i].w * inv;
        int srow = q0 + ty * 4 + i;
        *(float4*)&g_ctx[((size_t)(b * S_LEN + srow)) * DMODEL + h * DH + tx * 4] = r;
    }
}

// ---------------------------------------------------------------------------
// Output projection: out = ctx @ Wo + bo.  Same tiling as qkv_gemm.
// ---------------------------------------------------------------------------
__global__ __launch_bounds__(256) void proj_gemm(
    const float* __restrict__ Wo,
    const float* __restrict__ bo,
    float* __restrict__ out)
{
    __shared__ float As[16][132];
    __shared__ float Ws[16][64];

    const int bm = blockIdx.y * 128;
    const int bn = blockIdx.x * 64;
    const int tid = threadIdx.x;
    const int tx = tid & 15;
    const int ty = tid >> 4;

    float acc[8][4];
    #pragma unroll
    for (int i = 0; i < 8; i++)
        #pragma unroll
        for (int j = 0; j < 4; j++) acc[i][j] = 0.f;

    for (int k0 = 0; k0 < DMODEL; k0 += 16) {
        #pragma unroll
        for (int l = 0; l < 2; l++) {
            int idx = tid + l * 256;
            int row = idx >> 2;
            int c4  = idx & 3;
            float4 a = *(const float4*)&g_ctx[(size_t)(bm + row) * DMODEL + k0 + c4 * 4];
            As[c4*4 + 0][row] = a.x;
            As[c4*4 + 1][row] = a.y;
            As[c4*4 + 2][row] = a.z;
            As[c4*4 + 3][row] = a.w;
        }
        {
            int row = tid >> 4;
            int c4  = tid & 15;
            *(float4*)&Ws[row][c4 * 4] =
                *(const float4*)&Wo[(size_t)(k0 + row) * DMODEL + bn + c4 * 4];
        }
        __syncthreads();

        #pragma unroll
        for (int kk = 0; kk < 16; kk++) {
            float4 b = *(float4*)&Ws[kk][tx * 4];
            float a[8];
            #pragma unroll
            for (int i = 0; i < 8; i++) a[i] = As[kk][ty * 8 + i];
            #pragma unroll
            for (int i = 0; i < 8; i++) {
                acc[i][0] += a[i] * b.x;
                acc[i][1] += a[i] * b.y;
                acc[i][2] += a[i] * b.z;
                acc[i][3] += a[i] * b.w;
            }
        }
        __syncthreads();
    }

    float4 bb = *(const float4*)&bo[bn + tx * 4];
    #pragma unroll
    for (int i = 0; i < 8; i++) {
        int m = bm + ty * 8 + i;
        float4 r;
        r.x = acc[i][0] + bb.x;
        r.y = acc[i][1] + bb.y;
        r.z = acc[i][2] + bb.z;
        r.w = acc[i][3] + bb.w;
        *(float4*)&out[(size_t)m * DMODEL + bn + tx * 4] = r;
    }
}

// ---------------------------------------------------------------------------
extern "C" void kernel_launch(void* const* d_in, const int* in_sizes, int n_in,
                              void* d_out, int out_size)
{
    (void)in_sizes; (void)n_in; (void)out_size;
    const float* x  = (const float*)d_in[0];
    const float* Wq = (const float*)d_in[1];
    const float* Wk = (const float*)d_in[2];
    const float* Wv = (const float*)d_in[3];
    const float* Wo = (const float*)d_in[4];
    const float* bo = (const float*)d_in[5];
    float* out = (float*)d_out;

    // 1) QKV projections
    dim3 g1(DMODEL / 64, MROWS / 128, 3);
    qkv_gemm<<<g1, 256>>>(x, Wq, Wk, Wv);

    // 2) causal flash attention
    const int ATTN_SMEM = (64*64 + 64*68 + 64*64 + 64*68) * (int)sizeof(float); // 67584
    cudaFuncSetAttribute(attn_kernel, cudaFuncAttributeMaxDynamicSharedMemorySize, ATTN_SMEM);
    dim3 g2(S_LEN / 64, BATCH * NH);
    attn_kernel<<<g2, 256, ATTN_SMEM>>>();

    // 3) output projection + bias
    dim3 g3(DMODEL / 64, MROWS / 128);
    proj_gemm<<<g3, 256>>>(Wo, bo, out);
}

// round 16
// speedup vs baseline: 2.0742x; 2.0742x over previous
#include <cuda_runtime.h>
#include <math.h>

#define S_LEN 4096
#define DMODEL 768
#define NH 12
#define DH 64
#define BATCH 2
#define MROWS (BATCH*S_LEN)   // 8192
#define QSCALE 0.125f         // 1/sqrt(64), exact power of two

// Scratch (module-load allocated; no runtime allocs). Q/K/V hold tf32 bit patterns.
__device__ float g_Q[(size_t)BATCH*NH*S_LEN*DH];
__device__ float g_K[(size_t)BATCH*NH*S_LEN*DH];
__device__ float g_V[(size_t)BATCH*NH*S_LEN*DH];
__device__ float g_ctx[(size_t)MROWS*DMODEL];

__device__ __forceinline__ unsigned tf32r(float x) {
    unsigned u;
    asm("cvt.rna.tf32.f32 %0, %1;" : "=r"(u) : "f"(x));
    return u;
}

__device__ __forceinline__ void mma8(float* c,
                                     unsigned a0, unsigned a1, unsigned a2, unsigned a3,
                                     unsigned b0, unsigned b1) {
    asm volatile(
        "mma.sync.aligned.m16n8k8.row.col.f32.tf32.tf32.f32 "
        "{%0,%1,%2,%3}, {%4,%5,%6,%7}, {%8,%9}, {%0,%1,%2,%3};\n"
        : "+f"(c[0]), "+f"(c[1]), "+f"(c[2]), "+f"(c[3])
        : "r"(a0), "r"(a1), "r"(a2), "r"(a3), "r"(b0), "r"(b1));
}

// ---------------------------------------------------------------------------
// QKV GEMM (tf32 MMA): C = X @ W[z] -> [B,H,S,Dh] layout, tf32 bits stored.
// CTA 128x64, BK=16, 8 warps = 4(m) x 2(n), warp tile 32x32.
// ---------------------------------------------------------------------------
__global__ __launch_bounds__(256, 2) void qkv_gemm(
    const float* __restrict__ X,
    const float* __restrict__ Wq,
    const float* __restrict__ Wk,
    const float* __restrict__ Wv)
{
    const float* W = (blockIdx.z == 0) ? Wq : (blockIdx.z == 1) ? Wk : Wv;
    float* O       = (blockIdx.z == 0) ? g_Q : (blockIdx.z == 1) ? g_K : g_V;

    __shared__ unsigned sA[128 * 20];   // [row][k], stride 20 (conflict-free, 16B aligned)
    __shared__ unsigned sB[16 * 68];    // [k][n],   stride 68

    const int bm = blockIdx.y * 128;
    const int bn = blockIdx.x * 64;
    const int tid  = threadIdx.x;
    const int wid  = tid >> 5;
    const int lane = tid & 31;
    const int wm = wid & 3;
    const int wn = wid >> 2;
    const int g   = lane >> 2;
    const int tig = lane & 3;

    float c[2][4][4];
    #pragma unroll
    for (int im = 0; im < 2; im++)
        #pragma unroll
        for (int jn = 0; jn < 4; jn++)
            #pragma unroll
            for (int e = 0; e < 4; e++) c[im][jn][e] = 0.f;

    for (int k0 = 0; k0 < DMODEL; k0 += 16) {
        #pragma unroll
        for (int l = 0; l < 2; l++) {
            int idx = tid + 256 * l;
            int row = idx >> 2, c4 = idx & 3;
            float4 a = *(const float4*)&X[(size_t)(bm + row) * DMODEL + k0 + c4 * 4];
            uint4 u;
            u.x = tf32r(a.x); u.y = tf32r(a.y); u.z = tf32r(a.z); u.w = tf32r(a.w);
            *(uint4*)&sA[row * 20 + c4 * 4] = u;
        }
        {
            int row = tid >> 4, c4 = tid & 15;
            float4 b = *(const float4*)&W[(size_t)(k0 + row) * DMODEL + bn + c4 * 4];
            uint4 u;
            u.x = tf32r(b.x); u.y = tf32r(b.y); u.z = tf32r(b.z); u.w = tf32r(b.w);
            *(uint4*)&sB[row * 68 + c4 * 4] = u;
        }
        __syncthreads();

        #pragma unroll
        for (int kk = 0; kk < 2; kk++) {
            unsigned bf[4][2];
            #pragma unroll
            for (int jn = 0; jn < 4; jn++) {
                bf[jn][0] = sB[(kk * 8 + tig)     * 68 + wn * 32 + jn * 8 + g];
                bf[jn][1] = sB[(kk * 8 + tig + 4) * 68 + wn * 32 + jn * 8 + g];
            }
            #pragma unroll
            for (int im = 0; im < 2; im++) {
                int r = wm * 32 + im * 16 + g;
                unsigned a0 = sA[r       * 20 + kk * 8 + tig];
                unsigned a1 = sA[(r + 8) * 20 + kk * 8 + tig];
                unsigned a2 = sA[r       * 20 + kk * 8 + tig + 4];
                unsigned a3 = sA[(r + 8) * 20 + kk * 8 + tig + 4];
                #pragma unroll
                for (int jn = 0; jn < 4; jn++)
                    mma8(c[im][jn], a0, a1, a2, a3, bf[jn][0], bf[jn][1]);
            }
        }
        __syncthreads();
    }

    // Epilogue: fold Q scale, pre-round to tf32 bits, write [B,H,S,Dh].
    const float scale = (blockIdx.z == 0) ? QSCALE : 1.f;
    const int h = bn >> 6;
    #pragma unroll
    for (int im = 0; im < 2; im++) {
        #pragma unroll
        for (int jn = 0; jn < 4; jn++) {
            int row = bm + wm * 32 + im * 16 + g;
            int d   = wn * 32 + jn * 8 + tig * 2;
            #pragma unroll
            for (int rr = 0; rr < 2; rr++) {
                int r = row + rr * 8;
                int b = r >> 12;
                int s = r & (S_LEN - 1);
                uint2 u;
                u.x = tf32r(c[im][jn][rr * 2 + 0] * scale);
                u.y = tf32r(c[im][jn][rr * 2 + 1] * scale);
                *(uint2*)&O[(((size_t)(b * NH + h) * S_LEN) + s) * DH + d] = u;
            }
        }
    }
}

// ---------------------------------------------------------------------------
// Flash attention (causal) with tf32 MMA. CTA = (bh, 128-row q-tile),
// 8 warps, warp owns 16 q-rows x 64 cols. smem stride 68 -> conflict-free
// fragment loads. P round-trips through warp-private smem rows (__syncwarp).
// ---------------------------------------------------------------------------
__global__ __launch_bounds__(256, 2) void attn_kernel()
{
    extern __shared__ unsigned sm[];
    unsigned* sQ = sm;                // [128][68]
    unsigned* sK = sQ + 128 * 68;     // [64][68]
    unsigned* sV = sK + 64 * 68;      // [64][68]
    unsigned* sP = sV + 64 * 68;      // [128][68]

    const int bh  = blockIdx.y;
    const int qt2 = (int)(gridDim.x - 1u - blockIdx.x);   // heavy tiles first
    const int q0  = qt2 * 128;
    const int tid  = threadIdx.x;
    const int wid  = tid >> 5;
    const int lane = tid & 31;
    const int g    = lane >> 2;
    const int tig  = lane & 3;
    const int row_s = 16 * wid + g;

    const uint4* Qp = (const uint4*)(g_Q + (size_t)bh * S_LEN * DH + (size_t)q0 * DH);
    const uint4* Kb = (const uint4*)(g_K + (size_t)bh * S_LEN * DH);
    const uint4* Vb = (const uint4*)(g_V + (size_t)bh * S_LEN * DH);

    // stage Q tile (already tf32 bits, pre-scaled)
    #pragma unroll
    for (int l = 0; l < 8; l++) {
        int idx = tid + 256 * l;
        int row = idx >> 4, c4 = idx & 15;
        *(uint4*)&sQ[row * 68 + c4 * 4] = Qp[idx];
    }

    float o[8][4];
    #pragma unroll
    for (int jn = 0; jn < 8; jn++)
        #pragma unroll
        for (int e = 0; e < 4; e++) o[jn][e] = 0.f;
    float m0 = -1e30f, m1 = -1e30f, l0 = 0.f, l1 = 0.f;

    const int ktmax = 2 * qt2 + 1;
    for (int kt = 0; kt <= ktmax; kt++) {
        __syncthreads();   // prior PV reads done before overwriting K/V
        const uint4* Kp = Kb + (size_t)kt * 64 * (DH / 4);
        const uint4* Vp = Vb + (size_t)kt * 64 * (DH / 4);
        #pragma unroll
        for (int l = 0; l < 4; l++) {
            int idx = tid + 256 * l;
            int row = idx >> 4, c4 = idx & 15;
            *(uint4*)&sK[row * 68 + c4 * 4] = Kp[idx];
            *(uint4*)&sV[row * 68 + c4 * 4] = Vp[idx];
        }
        __syncthreads();

        // scores S = Q @ K^T  (warp rows row_s, row_s+8; cols jn*8 + tig*2,+1)
        float c[8][4];
        #pragma unroll
        for (int jn = 0; jn < 8; jn++)
            #pragma unroll
            for (int e = 0; e < 4; e++) c[jn][e] = 0.f;

        #pragma unroll
        for (int kk = 0; kk < 8; kk++) {
            unsigned a0 = sQ[row_s       * 68 + kk * 8 + tig];
            unsigned a1 = sQ[(row_s + 8) * 68 + kk * 8 + tig];
            unsigned a2 = sQ[row_s       * 68 + kk * 8 + tig + 4];
            unsigned a3 = sQ[(row_s + 8) * 68 + kk * 8 + tig + 4];
            #pragma unroll
            for (int jn = 0; jn < 8; jn++) {
                unsigned b0 = sK[(jn * 8 + g) * 68 + kk * 8 + tig];
                unsigned b1 = sK[(jn * 8 + g) * 68 + kk * 8 + tig + 4];
                mma8(c[jn], a0, a1, a2, a3, b0, b1);
            }
        }

        // causal mask (only the two diagonal-overlap tiles)
        if (kt >= 2 * qt2) {
            int colb = kt * 64 + tig * 2;
            int r0g = q0 + row_s, r1g = r0g + 8;
            #pragma unroll
            for (int jn = 0; jn < 8; jn++) {
                int cg = colb + jn * 8;
                if (cg     > r0g) c[jn][0] = -1e30f;
                if (cg + 1 > r0g) c[jn][1] = -1e30f;
                if (cg     > r1g) c[jn][2] = -1e30f;
                if (cg + 1 > r1g) c[jn][3] = -1e30f;
            }
        }

        // online softmax (quad lanes tig 0..3 share each row)
        float mx0 = -1e30f, mx1 = -1e30f;
        #pragma unroll
        for (int jn = 0; jn < 8; jn++) {
            mx0 = fmaxf(mx0, fmaxf(c[jn][0], c[jn][1]));
            mx1 = fmaxf(mx1, fmaxf(c[jn][2], c[jn][3]));
        }
        mx0 = fmaxf(mx0, __shfl_xor_sync(0xffffffffu, mx0, 1));
        mx0 = fmaxf(mx0, __shfl_xor_sync(0xffffffffu, mx0, 2));
        mx1 = fmaxf(mx1, __shfl_xor_sync(0xffffffffu, mx1, 1));
        mx1 = fmaxf(mx1, __shfl_xor_sync(0xffffffffu, mx1, 2));

        float mn0 = fmaxf(m0, mx0), mn1 = fmaxf(m1, mx1);
        float al0 = __expf(m0 - mn0), al1 = __expf(m1 - mn1);
        m0 = mn0; m1 = mn1;

        float s0 = 0.f, s1 = 0.f;
        #pragma unroll
        for (int jn = 0; jn < 8; jn++) {
            uint2 u0, u1;
            u0.x = tf32r(__expf(c[jn][0] - mn0));
            u0.y = tf32r(__expf(c[jn][1] - mn0));
            u1.x = tf32r(__expf(c[jn][2] - mn1));
            u1.y = tf32r(__expf(c[jn][3] - mn1));
            s0 += __uint_as_float(u0.x) + __uint_as_float(u0.y);
            s1 += __uint_as_float(u1.x) + __uint_as_float(u1.y);
            *(uint2*)&sP[row_s       * 68 + jn * 8 + tig * 2] = u0;
            *(uint2*)&sP[(row_s + 8) * 68 + jn * 8 + tig * 2] = u1;
        }
        s0 += __shfl_xor_sync(0xffffffffu, s0, 1);
        s0 += __shfl_xor_sync(0xffffffffu, s0, 2);
        s1 += __shfl_xor_sync(0xffffffffu, s1, 1);
        s1 += __shfl_xor_sync(0xffffffffu, s1, 2);
        l0 = l0 * al0 + s0;
        l1 = l1 * al1 + s1;
        #pragma unroll
        for (int jn = 0; jn < 8; jn++) {
            o[jn][0] *= al0; o[jn][1] *= al0;
            o[jn][2] *= al1; o[jn][3] *= al1;
        }
        __syncwarp();   // sP rows are warp-private: warp-level visibility only

        // O += P @ V
        #pragma unroll
        for (int kk = 0; kk < 8; kk++) {
            unsigned a0 = sP[row_s       * 68 + kk * 8 + tig];
            unsigned a1 = sP[(row_s + 8) * 68 + kk * 8 + tig];
            unsigned a2 = sP[row_s       * 68 + kk * 8 + tig + 4];
            unsigned a3 = sP[(row_s + 8) * 68 + kk * 8 + tig + 4];
            #pragma unroll
            for (int jn = 0; jn < 8; jn++) {
                unsigned b0 = sV[(kk * 8 + tig)     * 68 + jn * 8 + g];
                unsigned b1 = sV[(kk * 8 + tig + 4) * 68 + jn * 8 + g];
                mma8(o[jn], a0, a1, a2, a3, b0, b1);
            }
        }
    }

    // finalize -> g_ctx [b, s, h*64+d] (fp32)
    float i0 = 1.f / l0, i1 = 1.f / l1;
    int b = bh / NH, h = bh - b * NH;
    int r0g = q0 + row_s;
    float* base0 = g_ctx + ((size_t)(b * S_LEN + r0g)) * DMODEL + h * DH + tig * 2;
    float* base1 = base0 + (size_t)8 * DMODEL;
    #pragma unroll
    for (int jn = 0; jn < 8; jn++) {
        float2 v0, v1;
        v0.x = o[jn][0] * i0; v0.y = o[jn][1] * i0;
        v1.x = o[jn][2] * i1; v1.y = o[jn][3] * i1;
        *(float2*)&base0[jn * 8] = v0;
        *(float2*)&base1[jn * 8] = v1;
    }
}

// ---------------------------------------------------------------------------
// Output projection (tf32 MMA): out = ctx @ Wo + bo. Same tiling as qkv_gemm.
// ---------------------------------------------------------------------------
__global__ __launch_bounds__(256, 2) void proj_gemm(
    const float* __restrict__ Wo,
    const float* __restrict__ bo,
    float* __restrict__ out)
{
    __shared__ unsigned sA[128 * 20];
    __shared__ unsigned sB[16 * 68];

    const int bm = blockIdx.y * 128;
    const int bn = blockIdx.x * 64;
    const int tid  = threadIdx.x;
    const int wid  = tid >> 5;
    const int lane = tid & 31;
    const int wm = wid & 3;
    const int wn = wid >> 2;
    const int g   = lane >> 2;
    const int tig = lane & 3;

    float c[2][4][4];
    #pragma unroll
    for (int im = 0; im < 2; im++)
        #pragma unroll
        for (int jn = 0; jn < 4; jn++)
            #pragma unroll
            for (int e = 0; e < 4; e++) c[im][jn][e] = 0.f;

    for (int k0 = 0; k0 < DMODEL; k0 += 16) {
        #pragma unroll
        for (int l = 0; l < 2; l++) {
            int idx = tid + 256 * l;
            int row = idx >> 2, c4 = idx & 3;
            float4 a = *(const float4*)&g_ctx[(size_t)(bm + row) * DMODEL + k0 + c4 * 4];
            uint4 u;
            u.x = tf32r(a.x); u.y = tf32r(a.y); u.z = tf32r(a.z); u.w = tf32r(a.w);
            *(uint4*)&sA[row * 20 + c4 * 4] = u;
        }
        {
            int row = tid >> 4, c4 = tid & 15;
            float4 b = *(const float4*)&Wo[(size_t)(k0 + row) * DMODEL + bn + c4 * 4];
            uint4 u;
            u.x = tf32r(b.x); u.y = tf32r(b.y); u.z = tf32r(b.z); u.w = tf32r(b.w);
            *(uint4*)&sB[row * 68 + c4 * 4] = u;
        }
        __syncthreads();

        #pragma unroll
        for (int kk = 0; kk < 2; kk++) {
            unsigned bf[4][2];
            #pragma unroll
            for (int jn = 0; jn < 4; jn++) {
                bf[jn][0] = sB[(kk * 8 + tig)     * 68 + wn * 32 + jn * 8 + g];
                bf[jn][1] = sB[(kk * 8 + tig + 4) * 68 + wn * 32 + jn * 8 + g];
            }
            #pragma unroll
            for (int im = 0; im < 2; im++) {
                int r = wm * 32 + im * 16 + g;
                unsigned a0 = sA[r       * 20 + kk * 8 + tig];
                unsigned a1 = sA[(r + 8) * 20 + kk * 8 + tig];
                unsigned a2 = sA[r       * 20 + kk * 8 + tig + 4];
                unsigned a3 = sA[(r + 8) * 20 + kk * 8 + tig + 4];
                #pragma unroll
                for (int jn = 0; jn < 4; jn++)
                    mma8(c[im][jn], a0, a1, a2, a3, bf[jn][0], bf[jn][1]);
            }
        }
        __syncthreads();
    }

    #pragma unroll
    for (int im = 0; im < 2; im++) {
        #pragma unroll
        for (int jn = 0; jn < 4; jn++) {
            int row = bm + wm * 32 + im * 16 + g;
            int col = bn + wn * 32 + jn * 8 + tig * 2;
            float b0v = bo[col], b1v = bo[col + 1];
            #pragma unroll
            for (int rr = 0; rr < 2; rr++) {
                int r = row + rr * 8;
                float2 v;
                v.x = c[im][jn][rr * 2 + 0] + b0v;
                v.y = c[im][jn][rr * 2 + 1] + b1v;
                *(float2*)&out[(size_t)r * DMODEL + col] = v;
            }
        }
    }
}

// ---------------------------------------------------------------------------
extern "C" void kernel_launch(void* const* d_in, const int* in_sizes, int n_in,
                              void* d_out, int out_size)
{
    (void)in_sizes; (void)n_in; (void)out_size;
    const float* x  = (const float*)d_in[0];
    const float* Wq = (const float*)d_in[1];
    const float* Wk = (const float*)d_in[2];
    const float* Wv = (const float*)d_in[3];
    const float* Wo = (const float*)d_in[4];
    const float* bo = (const float*)d_in[5];
    float* out = (float*)d_out;

    // 1) QKV projections (tf32 tensor core)
    dim3 g1(DMODEL / 64, MROWS / 128, 3);
    qkv_gemm<<<g1, 256>>>(x, Wq, Wk, Wv);

    // 2) causal flash attention (tf32 tensor core)
    const int ATTN_SMEM = (128 + 64 + 64 + 128) * 68 * (int)sizeof(unsigned); // 104448
    cudaFuncSetAttribute(attn_kernel, cudaFuncAttributeMaxDynamicSharedMemorySize, ATTN_SMEM);
    dim3 g2(S_LEN / 128, BATCH * NH);
    attn_kernel<<<g2, 256, ATTN_SMEM>>>();

    // 3) output projection + bias
    dim3 g3(DMODEL / 64, MROWS / 128);
    proj_gemm<<<g3, 256>>>(Wo, bo, out);
}